// round 1
// baseline (speedup 1.0000x reference)
#include <cuda_runtime.h>

#define NT 256
#define NMI 64
#define NMA 16
#define DD 32
#define EHID 64

// ---- shared memory layout (float offsets) ----
#define o_WtdT  0
#define o_WqT   1024
#define o_WkT   2048
#define o_WvT   3072
#define o_WoT   4096
#define o_Wsmi  5120
#define o_Wami  6144
#define o_Wsma  7168
#define o_Wama  8192
#define o_We1   9216
#define o_Ami   11264
#define o_Ama   15360
#define o_btd   15616
#define o_lng   15648
#define o_lnb   15680
#define o_bo    15712
#define o_bmi   15744
#define o_bma   15776
#define o_bqkv  15808
#define o_be1   15904
#define o_We2   15968
#define o_Sa    16032
#define o_Sb    18080
#define o_Tmi   20128
#define o_Ma    21152
#define o_Mb    21664
#define o_Tma   22176
#define o_agg   23200
#define o_qp    25248
#define o_kpT   25760
#define o_vp    27840
#define o_sc    29888
#define o_misc  31936
#define SMEM_FLOATS 32000
#define SMEM_BYTES  (SMEM_FLOATS * 4)

__device__ __forceinline__ float warp_sum(float v) {
    #pragma unroll
    for (int o = 16; o; o >>= 1) v += __shfl_xor_sync(0xFFFFFFFFu, v, o);
    return v;
}
__device__ __forceinline__ float warp_max(float v) {
    #pragma unroll
    for (int o = 16; o; o >>= 1) v = fmaxf(v, __shfl_xor_sync(0xFFFFFFFFu, v, o));
    return v;
}

__global__ __launch_bounds__(NT)
void hm_kernel(
    const float* __restrict__ g_micro, const float* __restrict__ g_macro,
    const float* __restrict__ g_tmi,   const float* __restrict__ g_tma,
    const float* __restrict__ W_td,    const float* __restrict__ b_td,
    const float* __restrict__ ln_g,    const float* __restrict__ ln_b,
    const float* __restrict__ Wqkv,    const float* __restrict__ bqkv,
    const float* __restrict__ Wo,      const float* __restrict__ bo,
    const float* __restrict__ A_mi,    const float* __restrict__ Ws_mi,
    const float* __restrict__ Wa_mi,   const float* __restrict__ b_mi,
    const float* __restrict__ A_ma,    const float* __restrict__ Ws_ma,
    const float* __restrict__ Wa_ma,   const float* __restrict__ b_ma,
    const float* __restrict__ We1,     const float* __restrict__ be1,
    const float* __restrict__ We2,     const float* __restrict__ be2,
    const int*   __restrict__ steps_p,
    float* __restrict__ out, int B)
{
    extern __shared__ float sm[];
    const int tid  = threadIdx.x;
    const int lane = tid & 31;
    const int warp = tid >> 5;
    const int b    = blockIdx.x;
    if (b >= B) return;

    // ---- stage weights (transposed where used as x @ W.T) ----
    for (int i = tid; i < 1024; i += NT) {
        int d = i >> 5, e = i & 31;
        sm[o_WtdT + d*32 + e] = W_td[e*32 + d];
        sm[o_WqT  + d*32 + e] = Wqkv[e*32 + d];
        sm[o_WkT  + d*32 + e] = Wqkv[(32 + e)*32 + d];
        sm[o_WvT  + d*32 + e] = Wqkv[(64 + e)*32 + d];
        sm[o_WoT  + d*32 + e] = Wo[e*32 + d];
        sm[o_Wsmi + i] = Ws_mi[i];
        sm[o_Wami + i] = Wa_mi[i];
        sm[o_Wsma + i] = Ws_ma[i];
        sm[o_Wama + i] = Wa_ma[i];
    }
    for (int i = tid; i < 4096; i += NT) sm[o_Ami + i] = A_mi[i];
    for (int i = tid; i < 2048; i += NT) sm[o_We1 + i] = We1[i];
    for (int i = tid; i < 256;  i += NT) sm[o_Ama + i] = A_ma[i];
    if (tid < 32) {
        sm[o_btd + tid] = b_td[tid];  sm[o_lng + tid] = ln_g[tid];
        sm[o_lnb + tid] = ln_b[tid];  sm[o_bo  + tid] = bo[tid];
        sm[o_bmi + tid] = b_mi[tid];  sm[o_bma + tid] = b_ma[tid];
    }
    if (tid < 96) sm[o_bqkv + tid] = bqkv[tid];
    if (tid < 64) { sm[o_be1 + tid] = be1[tid]; sm[o_We2 + tid] = We2[tid]; }

    // ---- stage per-batch state ----
    for (int i = tid; i < 2048; i += NT) sm[o_Sa + i] = g_micro[(long long)b*2048 + i];
    for (int i = tid; i < 1024; i += NT) {
        sm[o_Tmi + i] = g_tmi[(long long)b*1024 + i];
        sm[o_Tma + i] = g_tma[(long long)b*1024 + i];
    }
    for (int i = tid; i < 512; i += NT) sm[o_Ma + i] = g_macro[(long long)b*512 + i];

    const int steps = *steps_p;
    const float be2v = *be2;
    float* S  = sm + o_Sa;  float* Sn = sm + o_Sb;
    float* M  = sm + o_Ma;  float* Mn = sm + o_Mb;
    __syncthreads();

    for (int it = 0; it < steps; ++it) {
        // ---- A: macro bias into micro ----
        if (tid < 32) {
            float s = 0.f;
            #pragma unroll
            for (int i = 0; i < NMA; i++) s += M[i*32 + tid];
            sm[o_misc + tid] = s * (1.f / NMA);
        }
        __syncthreads();
        if (tid < 32) {
            float s = sm[o_btd + tid];
            #pragma unroll 8
            for (int d = 0; d < 32; d++) s += sm[o_misc + d] * sm[o_WtdT + d*32 + tid];
            sm[o_misc + 32 + tid] = s;
        }
        __syncthreads();
        for (int i = tid; i < 2048; i += NT) S[i] += 0.1f * sm[o_misc + 32 + (i & 31)];
        __syncthreads();

        // ---- B1: agg = A_mi @ S ----
        {
            float acc[8];
            #pragma unroll
            for (int k = 0; k < 8; k++) acc[k] = 0.f;
            #pragma unroll 4
            for (int n = 0; n < NMI; n++) {
                float s = S[n*32 + lane];
                #pragma unroll
                for (int k = 0; k < 8; k++)
                    acc[k] += sm[o_Ami + (warp + 8*k)*64 + n] * s;
            }
            #pragma unroll
            for (int k = 0; k < 8; k++) sm[o_agg + (warp + 8*k)*32 + lane] = acc[k];
        }
        __syncthreads();

        // ---- B2+B3: update = tanh(agg@Wa + S@(Ws+Tmi) + b); new = l2norm(S + 0.1 u) ----
        {
            float acc[8];
            #pragma unroll
            for (int k = 0; k < 8; k++) acc[k] = sm[o_bmi + lane];
            #pragma unroll 4
            for (int d = 0; d < 32; d++) {
                float wa  = sm[o_Wami + d*32 + lane];
                float wst = sm[o_Wsmi + d*32 + lane] + sm[o_Tmi + d*32 + lane];
                #pragma unroll
                for (int k = 0; k < 8; k++) {
                    int n = warp + 8*k;
                    acc[k] += sm[o_agg + n*32 + d] * wa + S[n*32 + d] * wst;
                }
            }
            #pragma unroll
            for (int k = 0; k < 8; k++) {
                int n = warp + 8*k;
                float v = S[n*32 + lane] + 0.1f * tanhf(acc[k]);
                float ss = warp_sum(v * v);
                Sn[n*32 + lane] = v * (1.f / (sqrtf(ss) + 1e-6f));
            }
        }
        __syncthreads();

        // ---- B4: micro trace update (uses old S and new Sn) ----
        {
            float acc[4] = {0.f, 0.f, 0.f, 0.f};
            #pragma unroll 4
            for (int n = 0; n < NMI; n++) {
                float snv = Sn[n*32 + lane];
                #pragma unroll
                for (int k = 0; k < 4; k++) acc[k] += S[n*32 + warp + 8*k] * snv;
            }
            #pragma unroll
            for (int k = 0; k < 4; k++) {
                int d = warp + 8*k;
                sm[o_Tmi + d*32 + lane] = 0.95f * sm[o_Tmi + d*32 + lane]
                                        + (0.05f / NMI) * acc[k];
            }
        }
        { float* t = S; S = Sn; Sn = t; }
        __syncthreads();

        // ---- C1: qp = M @ Wq.T + bq ----
        {
            float a0 = sm[o_bqkv + lane], a1 = a0;
            #pragma unroll 4
            for (int d = 0; d < 32; d++) {
                float w = sm[o_WqT + d*32 + lane];
                a0 += M[warp*32 + d] * w;
                a1 += M[(warp + 8)*32 + d] * w;
            }
            sm[o_qp + warp*32 + lane] = a0;
            sm[o_qp + (warp + 8)*32 + lane] = a1;
        }
        // ---- C2: kp (transposed, padded), vp from new micro S ----
        {
            float ak[8], av[8];
            #pragma unroll
            for (int k = 0; k < 8; k++) { ak[k] = sm[o_bqkv + 32 + lane]; av[k] = sm[o_bqkv + 64 + lane]; }
            #pragma unroll 4
            for (int d = 0; d < 32; d++) {
                float wk = sm[o_WkT + d*32 + lane];
                float wv = sm[o_WvT + d*32 + lane];
                #pragma unroll
                for (int k = 0; k < 8; k++) {
                    float sv = S[(warp + 8*k)*32 + d];
                    ak[k] += sv * wk;  av[k] += sv * wv;
                }
            }
            #pragma unroll
            for (int k = 0; k < 8; k++) {
                int row = warp + 8*k;
                sm[o_kpT + lane*65 + row] = ak[k];   // (lane*65+row)%32 conflict-free
                sm[o_vp + row*32 + lane]  = av[k];
            }
        }
        __syncthreads();

        // ---- C3: scores + fused softmax (rows r=(h,i), warp-owned) ----
        {
            #pragma unroll
            for (int j = 0; j < 4; j++) {
                int r = warp + 8*j;          // 0..31
                int h = r >> 4, i = r & 15;
                float a0 = 0.f, a1 = 0.f;
                #pragma unroll
                for (int dh = 0; dh < 16; dh++) {
                    int e = h*16 + dh;
                    float q = sm[o_qp + i*32 + e];
                    a0 += q * sm[o_kpT + e*65 + lane];
                    a1 += q * sm[o_kpT + e*65 + lane + 32];
                }
                a0 *= 0.25f; a1 *= 0.25f;
                float mx = warp_max(fmaxf(a0, a1));
                float e0 = __expf(a0 - mx), e1 = __expf(a1 - mx);
                float s = warp_sum(e0 + e1);
                float inv = 1.f / s;
                sm[o_sc + r*64 + lane]      = e0 * inv;
                sm[o_sc + r*64 + lane + 32] = e1 * inv;
            }
        }
        __syncthreads();

        // ---- C4a: att = attn @ v  (into agg scratch) ----
        {
            int h = lane >> 4;
            float a0 = 0.f, a1 = 0.f;
            #pragma unroll 4
            for (int k = 0; k < NMI; k++) {
                float v = sm[o_vp + k*32 + lane];
                a0 += sm[o_sc + (h*16 + warp)*64 + k] * v;
                a1 += sm[o_sc + (h*16 + warp + 8)*64 + k] * v;
            }
            sm[o_agg + warp*32 + lane] = a0;
            sm[o_agg + (warp + 8)*32 + lane] = a1;
        }
        __syncthreads();

        // ---- C4b: out proj + residual + layernorm -> Mn ----
        {
            #pragma unroll
            for (int k = 0; k < 2; k++) {
                int i = warp + 8*k;
                float acc = sm[o_bo + lane];
                #pragma unroll 4
                for (int d = 0; d < 32; d++)
                    acc += sm[o_agg + i*32 + d] * sm[o_WoT + d*32 + lane];
                float x = M[i*32 + lane] + acc;
                float mu = warp_sum(x) * (1.f / 32.f);
                float c = x - mu;
                float var = warp_sum(c * c) * (1.f / 32.f);
                Mn[i*32 + lane] = c * rsqrtf(var + 1e-5f) * sm[o_lng + lane] + sm[o_lnb + lane];
            }
        }
        __syncthreads();
        { float* t = M; M = Mn; Mn = t; }   // M = layernormed macro

        // ---- D1: macro agg = A_ma @ M ----
        {
            float a0 = 0.f, a1 = 0.f;
            #pragma unroll
            for (int n = 0; n < NMA; n++) {
                float s = M[n*32 + lane];
                a0 += sm[o_Ama + warp*16 + n] * s;
                a1 += sm[o_Ama + (warp + 8)*16 + n] * s;
            }
            sm[o_agg + warp*32 + lane] = a0;
            sm[o_agg + (warp + 8)*32 + lane] = a1;
        }
        __syncthreads();

        // ---- D2: macro update + l2norm -> Mn ----
        {
            #pragma unroll
            for (int k = 0; k < 2; k++) {
                int n = warp + 8*k;
                float acc = sm[o_bma + lane];
                #pragma unroll 4
                for (int d = 0; d < 32; d++) {
                    float sv = M[n*32 + d];
                    acc += sm[o_agg + n*32 + d] * sm[o_Wama + d*32 + lane]
                         + sv * (sm[o_Wsma + d*32 + lane] + sm[o_Tma + d*32 + lane]);
                }
                float v = M[n*32 + lane] + 0.1f * tanhf(acc);
                float ss = warp_sum(v * v);
                Mn[n*32 + lane] = v * (1.f / (sqrtf(ss) + 1e-6f));
            }
        }
        __syncthreads();

        // ---- D4: macro trace update ----
        {
            float acc[4] = {0.f, 0.f, 0.f, 0.f};
            #pragma unroll
            for (int n = 0; n < NMA; n++) {
                float snv = Mn[n*32 + lane];
                #pragma unroll
                for (int k = 0; k < 4; k++) acc[k] += M[n*32 + warp + 8*k] * snv;
            }
            #pragma unroll
            for (int k = 0; k < 4; k++) {
                int d = warp + 8*k;
                sm[o_Tma + d*32 + lane] = 0.95f * sm[o_Tma + d*32 + lane]
                                        + (0.05f / NMA) * acc[k];
            }
        }
        { float* t = M; M = Mn; Mn = t; }
        __syncthreads();
    }

    // ---- energy (only final iteration matters) ----
    {
        float part = 0.f;
        #pragma unroll
        for (int k = 0; k < 8; k++) {
            int n = warp + 8*k;
            float a0 = sm[o_be1 + lane], a1 = sm[o_be1 + lane + 32];
            #pragma unroll 4
            for (int d = 0; d < 32; d++) {
                float sv = S[n*32 + d];
                a0 += sv * sm[o_We1 + d*64 + lane];
                a1 += sv * sm[o_We1 + d*64 + lane + 32];
            }
            part += tanhf(a0) * sm[o_We2 + lane] + tanhf(a1) * sm[o_We2 + lane + 32];
        }
        part = warp_sum(part);
        if (lane == 0) sm[o_misc + warp] = part;
        __syncthreads();
        if (tid == 0) {
            float tot = 0.f;
            #pragma unroll
            for (int w = 0; w < 8; w++) tot += sm[o_misc + w];
            sm[o_misc + 16] = tot * (1.f / NMI) + be2v;
        }
    }
    __syncthreads();

    // ---- write outputs: micro | macro | tmi | tma | energy ----
    const long long off_micro = 0;
    const long long off_macro = (long long)B * 2048;
    const long long off_tmi   = off_macro + (long long)B * 512;
    const long long off_tma   = off_tmi   + (long long)B * 1024;
    const long long off_en    = off_tma   + (long long)B * 1024;
    for (int i = tid; i < 2048; i += NT) out[off_micro + (long long)b*2048 + i] = S[i];
    for (int i = tid; i < 512;  i += NT) out[off_macro + (long long)b*512  + i] = M[i];
    for (int i = tid; i < 1024; i += NT) {
        out[off_tmi + (long long)b*1024 + i] = sm[o_Tmi + i];
        out[off_tma + (long long)b*1024 + i] = sm[o_Tma + i];
    }
    if (tid == 0) out[off_en + b] = sm[o_misc + 16];
}

extern "C" void kernel_launch(void* const* d_in, const int* in_sizes, int n_in,
                              void* d_out, int out_size)
{
    const int B = in_sizes[0] / (NMI * DD);
    cudaFuncSetAttribute(hm_kernel, cudaFuncAttributeMaxDynamicSharedMemorySize, SMEM_BYTES);
    hm_kernel<<<B, NT, SMEM_BYTES>>>(
        (const float*)d_in[0],  (const float*)d_in[1],  (const float*)d_in[2],
        (const float*)d_in[3],  (const float*)d_in[4],  (const float*)d_in[5],
        (const float*)d_in[6],  (const float*)d_in[7],  (const float*)d_in[8],
        (const float*)d_in[9],  (const float*)d_in[10], (const float*)d_in[11],
        (const float*)d_in[12], (const float*)d_in[13], (const float*)d_in[14],
        (const float*)d_in[15], (const float*)d_in[16], (const float*)d_in[17],
        (const float*)d_in[18], (const float*)d_in[19], (const float*)d_in[20],
        (const float*)d_in[21], (const float*)d_in[22], (const float*)d_in[23],
        (const int*)d_in[24],
        (float*)d_out, B);
}

// round 2
// speedup vs baseline: 1.5643x; 1.5643x over previous
#include <cuda_runtime.h>

#define NT 512
#define NMI 64
#define NMA 16
#define DD 32

// ---- weight region (float offsets, shared by both groups) ----
#define o_WtdT  0
#define o_WqT   1024
#define o_WkT   2048
#define o_WvT   3072
#define o_WoT   4096
#define o_Wsmi  5120
#define o_Wami  6144
#define o_Wsma  7168
#define o_Wama  8192
#define o_We1   9216
#define o_Ami   11264
#define o_Ama   15360
#define o_btd   15616
#define o_lng   15648
#define o_lnb   15680
#define o_bo    15712
#define o_bmi   15744
#define o_bma   15776
#define o_bqkv  15808
#define o_be1   15904
#define o_We2   15968
#define W_FLOATS 16032

// ---- per-group state region (relative float offsets) ----
#define r_Sa    0
#define r_Sb    2048
#define r_Tmi   4096
#define r_Ma    5120
#define r_Mb    5632
#define r_Tma   6144
#define r_agg   7168
#define r_qp    9216
#define r_kpT   9728
#define r_vp    11808
#define r_sc    13856
#define r_misc  15904
#define ST_FLOATS 15968

#define SMEM_FLOATS (W_FLOATS + 2*ST_FLOATS)
#define SMEM_BYTES  (SMEM_FLOATS * 4)

__device__ __forceinline__ float warp_sum(float v) {
    #pragma unroll
    for (int o = 16; o; o >>= 1) v += __shfl_xor_sync(0xFFFFFFFFu, v, o);
    return v;
}
__device__ __forceinline__ float warp_max(float v) {
    #pragma unroll
    for (int o = 16; o; o >>= 1) v = fmaxf(v, __shfl_xor_sync(0xFFFFFFFFu, v, o));
    return v;
}
__device__ __forceinline__ void gbar(int wg) {
    asm volatile("bar.sync %0, 256;" :: "r"(wg + 1) : "memory");
}
__device__ __forceinline__ float4 ld4(const float* p) {
    return *reinterpret_cast<const float4*>(p);
}

__global__ __launch_bounds__(NT)
void hm_kernel(
    const float* __restrict__ g_micro, const float* __restrict__ g_macro,
    const float* __restrict__ g_tmi,   const float* __restrict__ g_tma,
    const float* __restrict__ W_td,    const float* __restrict__ b_td,
    const float* __restrict__ ln_g,    const float* __restrict__ ln_b,
    const float* __restrict__ Wqkv,    const float* __restrict__ bqkv,
    const float* __restrict__ Wo,      const float* __restrict__ bo,
    const float* __restrict__ A_mi,    const float* __restrict__ Ws_mi,
    const float* __restrict__ Wa_mi,   const float* __restrict__ b_mi,
    const float* __restrict__ A_ma,    const float* __restrict__ Ws_ma,
    const float* __restrict__ Wa_ma,   const float* __restrict__ b_ma,
    const float* __restrict__ We1,     const float* __restrict__ be1,
    const float* __restrict__ We2,     const float* __restrict__ be2,
    const int*   __restrict__ steps_p,
    float* __restrict__ out, int B)
{
    extern __shared__ float sm[];
    const int tid   = threadIdx.x;
    const int lane  = tid & 31;
    const int wg    = tid >> 8;           // batch group 0/1
    const int tid_g = tid & 255;
    const int warp  = tid_g >> 5;         // 0..7 within group

    int b = blockIdx.x * 2 + wg;
    const bool valid = (b < B);
    if (!valid) b = B - 1;                // duplicate work, skip writes

    // ---- stage weights (all 512 threads) ----
    for (int i = tid; i < 1024; i += NT) {
        int d = i >> 5, e = i & 31;
        sm[o_WtdT + d*32 + e] = W_td[e*32 + d];
        sm[o_WqT  + d*32 + e] = Wqkv[e*32 + d];
        sm[o_WkT  + d*32 + e] = Wqkv[(32 + e)*32 + d];
        sm[o_WvT  + d*32 + e] = Wqkv[(64 + e)*32 + d];
        sm[o_WoT  + d*32 + e] = Wo[e*32 + d];
        sm[o_Wsmi + i] = Ws_mi[i];
        sm[o_Wami + i] = Wa_mi[i];
        sm[o_Wsma + i] = Ws_ma[i];
        sm[o_Wama + i] = Wa_ma[i];
    }
    for (int i = tid; i < 4096; i += NT) sm[o_Ami + i] = A_mi[i];
    for (int i = tid; i < 2048; i += NT) sm[o_We1 + i] = We1[i];
    for (int i = tid; i < 256;  i += NT) sm[o_Ama + i] = A_ma[i];
    if (tid < 32) {
        sm[o_btd + tid] = b_td[tid];  sm[o_lng + tid] = ln_g[tid];
        sm[o_lnb + tid] = ln_b[tid];  sm[o_bo  + tid] = bo[tid];
        sm[o_bmi + tid] = b_mi[tid];  sm[o_bma + tid] = b_ma[tid];
    }
    if (tid >= 32 && tid < 128) sm[o_bqkv + tid - 32] = bqkv[tid - 32];
    if (tid >= 128 && tid < 192) sm[o_be1 + tid - 128] = be1[tid - 128];
    if (tid >= 192 && tid < 256) sm[o_We2 + tid - 192] = We2[tid - 192];

    // ---- stage per-group state ----
    float* st = sm + W_FLOATS + wg * ST_FLOATS;
    for (int i = tid_g; i < 2048; i += 256) st[r_Sa + i] = g_micro[(long long)b*2048 + i];
    for (int i = tid_g; i < 1024; i += 256) {
        st[r_Tmi + i] = g_tmi[(long long)b*1024 + i];
        st[r_Tma + i] = g_tma[(long long)b*1024 + i];
    }
    for (int i = tid_g; i < 512; i += 256) st[r_Ma + i] = g_macro[(long long)b*512 + i];

    const int steps = *steps_p;
    const float be2v = *be2;
    float* S  = st + r_Sa;  float* Sn = st + r_Sb;
    float* M  = st + r_Ma;  float* Mn = st + r_Mb;
    float* agg = st + r_agg;
    float* qp  = st + r_qp;
    float* kpT = st + r_kpT;
    float* vp  = st + r_vp;
    float* sc  = st + r_sc;
    float* misc = st + r_misc;
    __syncthreads();

    for (int it = 0; it < steps; ++it) {
        // ---- A: macro bias into micro ----
        if (tid_g < 32) {
            float s = 0.f;
            #pragma unroll
            for (int i = 0; i < NMA; i++) s += M[i*32 + tid_g];
            misc[tid_g] = s * (1.f / NMA);
        }
        gbar(wg);
        if (tid_g < 32) {
            float s = sm[o_btd + tid_g];
            #pragma unroll 8
            for (int d = 0; d < 32; d++) s += misc[d] * sm[o_WtdT + d*32 + tid_g];
            misc[32 + tid_g] = s;
        }
        gbar(wg);
        for (int i = tid_g; i < 2048; i += 256) S[i] += 0.1f * misc[32 + (i & 31)];
        gbar(wg);

        // ---- B1: agg = A_mi @ S ----
        {
            float acc[8];
            #pragma unroll
            for (int k = 0; k < 8; k++) acc[k] = 0.f;
            #pragma unroll 4
            for (int n4 = 0; n4 < 16; n4++) {
                float s0 = S[(4*n4+0)*32 + lane];
                float s1 = S[(4*n4+1)*32 + lane];
                float s2 = S[(4*n4+2)*32 + lane];
                float s3 = S[(4*n4+3)*32 + lane];
                #pragma unroll
                for (int k = 0; k < 8; k++) {
                    float4 a = ld4(&sm[o_Ami + (warp + 8*k)*64 + 4*n4]);
                    acc[k] += a.x*s0 + a.y*s1 + a.z*s2 + a.w*s3;
                }
            }
            #pragma unroll
            for (int k = 0; k < 8; k++) agg[(warp + 8*k)*32 + lane] = acc[k];
        }
        gbar(wg);

        // ---- B2+B3: update = tanh(agg@Wa + S@(Ws+Tmi) + b); Sn = l2norm(S + 0.1u) ----
        {
            float acc[8];
            #pragma unroll
            for (int k = 0; k < 8; k++) acc[k] = sm[o_bmi + lane];
            #pragma unroll 2
            for (int d4 = 0; d4 < 8; d4++) {
                float wa0 = sm[o_Wami + (4*d4+0)*32 + lane];
                float wa1 = sm[o_Wami + (4*d4+1)*32 + lane];
                float wa2 = sm[o_Wami + (4*d4+2)*32 + lane];
                float wa3 = sm[o_Wami + (4*d4+3)*32 + lane];
                float w0 = sm[o_Wsmi + (4*d4+0)*32 + lane] + st[r_Tmi + (4*d4+0)*32 + lane];
                float w1 = sm[o_Wsmi + (4*d4+1)*32 + lane] + st[r_Tmi + (4*d4+1)*32 + lane];
                float w2 = sm[o_Wsmi + (4*d4+2)*32 + lane] + st[r_Tmi + (4*d4+2)*32 + lane];
                float w3 = sm[o_Wsmi + (4*d4+3)*32 + lane] + st[r_Tmi + (4*d4+3)*32 + lane];
                #pragma unroll
                for (int k = 0; k < 8; k++) {
                    int n = warp + 8*k;
                    float4 ag = ld4(&agg[n*32 + 4*d4]);
                    float4 s4 = ld4(&S[n*32 + 4*d4]);
                    acc[k] += ag.x*wa0 + ag.y*wa1 + ag.z*wa2 + ag.w*wa3
                            + s4.x*w0  + s4.y*w1  + s4.z*w2  + s4.w*w3;
                }
            }
            #pragma unroll
            for (int k = 0; k < 8; k++) {
                int n = warp + 8*k;
                float v = S[n*32 + lane] + 0.1f * tanhf(acc[k]);
                float ss = warp_sum(v * v);
                Sn[n*32 + lane] = v * (1.f / (sqrtf(ss) + 1e-6f));
            }
        }
        gbar(wg);

        // ---- B4: micro trace (cols d = 4*warp + k, contiguous float4 bcast) ----
        {
            float acc[4] = {0.f, 0.f, 0.f, 0.f};
            #pragma unroll 8
            for (int n = 0; n < NMI; n++) {
                float snv = Sn[n*32 + lane];
                float4 sv = ld4(&S[n*32 + 4*warp]);
                acc[0] += sv.x*snv; acc[1] += sv.y*snv;
                acc[2] += sv.z*snv; acc[3] += sv.w*snv;
            }
            #pragma unroll
            for (int k = 0; k < 4; k++) {
                int d = 4*warp + k;
                st[r_Tmi + d*32 + lane] = 0.95f * st[r_Tmi + d*32 + lane]
                                        + (0.05f / NMI) * acc[k];
            }
        }
        { float* t = S; S = Sn; Sn = t; }
        gbar(wg);

        // ---- C1: qp = M @ Wq.T + bq ----
        {
            float a0 = sm[o_bqkv + lane], a1 = a0;
            #pragma unroll
            for (int d4 = 0; d4 < 8; d4++) {
                float q0 = sm[o_WqT + (4*d4+0)*32 + lane];
                float q1 = sm[o_WqT + (4*d4+1)*32 + lane];
                float q2 = sm[o_WqT + (4*d4+2)*32 + lane];
                float q3 = sm[o_WqT + (4*d4+3)*32 + lane];
                float4 m0 = ld4(&M[warp*32 + 4*d4]);
                float4 m1 = ld4(&M[(warp+8)*32 + 4*d4]);
                a0 += m0.x*q0 + m0.y*q1 + m0.z*q2 + m0.w*q3;
                a1 += m1.x*q0 + m1.y*q1 + m1.z*q2 + m1.w*q3;
            }
            qp[warp*32 + lane] = a0;
            qp[(warp+8)*32 + lane] = a1;
        }
        // ---- C2: kp (transposed, padded) + vp from new micro S ----
        {
            float ak[8], av[8];
            #pragma unroll
            for (int k = 0; k < 8; k++) { ak[k] = sm[o_bqkv + 32 + lane]; av[k] = sm[o_bqkv + 64 + lane]; }
            #pragma unroll 2
            for (int d4 = 0; d4 < 8; d4++) {
                float k0 = sm[o_WkT + (4*d4+0)*32 + lane];
                float k1 = sm[o_WkT + (4*d4+1)*32 + lane];
                float k2 = sm[o_WkT + (4*d4+2)*32 + lane];
                float k3 = sm[o_WkT + (4*d4+3)*32 + lane];
                float v0 = sm[o_WvT + (4*d4+0)*32 + lane];
                float v1 = sm[o_WvT + (4*d4+1)*32 + lane];
                float v2 = sm[o_WvT + (4*d4+2)*32 + lane];
                float v3 = sm[o_WvT + (4*d4+3)*32 + lane];
                #pragma unroll
                for (int k = 0; k < 8; k++) {
                    float4 s4 = ld4(&S[(warp + 8*k)*32 + 4*d4]);
                    ak[k] += s4.x*k0 + s4.y*k1 + s4.z*k2 + s4.w*k3;
                    av[k] += s4.x*v0 + s4.y*v1 + s4.z*v2 + s4.w*v3;
                }
            }
            #pragma unroll
            for (int k = 0; k < 8; k++) {
                int row = warp + 8*k;
                kpT[lane*65 + row] = ak[k];
                vp[row*32 + lane]  = av[k];
            }
        }
        gbar(wg);

        // ---- C3: scores + fused softmax ----
        {
            #pragma unroll
            for (int j = 0; j < 4; j++) {
                int r = warp + 8*j;          // 0..31
                int h = r >> 4, i = r & 15;
                float a0 = 0.f, a1 = 0.f;
                #pragma unroll
                for (int c = 0; c < 4; c++) {
                    float4 q4 = ld4(&qp[i*32 + h*16 + 4*c]);
                    int e = h*16 + 4*c;
                    a0 += q4.x * kpT[(e+0)*65 + lane] + q4.y * kpT[(e+1)*65 + lane]
                        + q4.z * kpT[(e+2)*65 + lane] + q4.w * kpT[(e+3)*65 + lane];
                    a1 += q4.x * kpT[(e+0)*65 + lane + 32] + q4.y * kpT[(e+1)*65 + lane + 32]
                        + q4.z * kpT[(e+2)*65 + lane + 32] + q4.w * kpT[(e+3)*65 + lane + 32];
                }
                a0 *= 0.25f; a1 *= 0.25f;
                float mx = warp_max(fmaxf(a0, a1));
                float e0 = __expf(a0 - mx), e1 = __expf(a1 - mx);
                float s = warp_sum(e0 + e1);
                float inv = 1.f / s;
                sc[r*64 + lane]      = e0 * inv;
                sc[r*64 + lane + 32] = e1 * inv;
            }
        }
        gbar(wg);

        // ---- C4a: att = attn @ v ----
        {
            int h = lane >> 4;
            float a0 = 0.f, a1 = 0.f;
            #pragma unroll 4
            for (int k4 = 0; k4 < 16; k4++) {
                float4 p0 = ld4(&sc[(h*16 + warp)*64 + 4*k4]);
                float4 p1 = ld4(&sc[(h*16 + warp + 8)*64 + 4*k4]);
                float v0 = vp[(4*k4+0)*32 + lane];
                float v1 = vp[(4*k4+1)*32 + lane];
                float v2 = vp[(4*k4+2)*32 + lane];
                float v3 = vp[(4*k4+3)*32 + lane];
                a0 += p0.x*v0 + p0.y*v1 + p0.z*v2 + p0.w*v3;
                a1 += p1.x*v0 + p1.y*v1 + p1.z*v2 + p1.w*v3;
            }
            agg[warp*32 + lane] = a0;
            agg[(warp+8)*32 + lane] = a1;
        }
        gbar(wg);

        // ---- C4b: out proj + residual + layernorm -> Mn ----
        {
            #pragma unroll
            for (int k = 0; k < 2; k++) {
                int i = warp + 8*k;
                float acc = sm[o_bo + lane];
                #pragma unroll
                for (int d4 = 0; d4 < 8; d4++) {
                    float o0 = sm[o_WoT + (4*d4+0)*32 + lane];
                    float o1 = sm[o_WoT + (4*d4+1)*32 + lane];
                    float o2 = sm[o_WoT + (4*d4+2)*32 + lane];
                    float o3 = sm[o_WoT + (4*d4+3)*32 + lane];
                    float4 g4 = ld4(&agg[i*32 + 4*d4]);
                    acc += g4.x*o0 + g4.y*o1 + g4.z*o2 + g4.w*o3;
                }
                float x = M[i*32 + lane] + acc;
                float mu = warp_sum(x) * (1.f / 32.f);
                float c = x - mu;
                float var = warp_sum(c * c) * (1.f / 32.f);
                Mn[i*32 + lane] = c * rsqrtf(var + 1e-5f) * sm[o_lng + lane] + sm[o_lnb + lane];
            }
        }
        gbar(wg);
        { float* t = M; M = Mn; Mn = t; }

        // ---- D1: macro agg = A_ma @ M ----
        {
            float a0 = 0.f, a1 = 0.f;
            #pragma unroll
            for (int n4 = 0; n4 < 4; n4++) {
                float s0 = M[(4*n4+0)*32 + lane];
                float s1 = M[(4*n4+1)*32 + lane];
                float s2 = M[(4*n4+2)*32 + lane];
                float s3 = M[(4*n4+3)*32 + lane];
                float4 aa = ld4(&sm[o_Ama + warp*16 + 4*n4]);
                float4 ab = ld4(&sm[o_Ama + (warp+8)*16 + 4*n4]);
                a0 += aa.x*s0 + aa.y*s1 + aa.z*s2 + aa.w*s3;
                a1 += ab.x*s0 + ab.y*s1 + ab.z*s2 + ab.w*s3;
            }
            agg[warp*32 + lane] = a0;
            agg[(warp+8)*32 + lane] = a1;
        }
        gbar(wg);

        // ---- D2: macro update + l2norm -> Mn ----
        {
            float acc0 = sm[o_bma + lane], acc1 = acc0;
            #pragma unroll 2
            for (int d4 = 0; d4 < 8; d4++) {
                float wa0 = sm[o_Wama + (4*d4+0)*32 + lane];
                float wa1 = sm[o_Wama + (4*d4+1)*32 + lane];
                float wa2 = sm[o_Wama + (4*d4+2)*32 + lane];
                float wa3 = sm[o_Wama + (4*d4+3)*32 + lane];
                float w0 = sm[o_Wsma + (4*d4+0)*32 + lane] + st[r_Tma + (4*d4+0)*32 + lane];
                float w1 = sm[o_Wsma + (4*d4+1)*32 + lane] + st[r_Tma + (4*d4+1)*32 + lane];
                float w2 = sm[o_Wsma + (4*d4+2)*32 + lane] + st[r_Tma + (4*d4+2)*32 + lane];
                float w3 = sm[o_Wsma + (4*d4+3)*32 + lane] + st[r_Tma + (4*d4+3)*32 + lane];
                float4 g0 = ld4(&agg[warp*32 + 4*d4]);
                float4 m0 = ld4(&M[warp*32 + 4*d4]);
                float4 g1 = ld4(&agg[(warp+8)*32 + 4*d4]);
                float4 m1 = ld4(&M[(warp+8)*32 + 4*d4]);
                acc0 += g0.x*wa0 + g0.y*wa1 + g0.z*wa2 + g0.w*wa3
                      + m0.x*w0  + m0.y*w1  + m0.z*w2  + m0.w*w3;
                acc1 += g1.x*wa0 + g1.y*wa1 + g1.z*wa2 + g1.w*wa3
                      + m1.x*w0  + m1.y*w1  + m1.z*w2  + m1.w*w3;
            }
            {
                float v = M[warp*32 + lane] + 0.1f * tanhf(acc0);
                float ss = warp_sum(v * v);
                Mn[warp*32 + lane] = v * (1.f / (sqrtf(ss) + 1e-6f));
            }
            {
                float v = M[(warp+8)*32 + lane] + 0.1f * tanhf(acc1);
                float ss = warp_sum(v * v);
                Mn[(warp+8)*32 + lane] = v * (1.f / (sqrtf(ss) + 1e-6f));
            }
        }
        gbar(wg);

        // ---- D4: macro trace (cols d = 4*warp + k) ----
        {
            float acc[4] = {0.f, 0.f, 0.f, 0.f};
            #pragma unroll
            for (int n = 0; n < NMA; n++) {
                float snv = Mn[n*32 + lane];
                float4 sv = ld4(&M[n*32 + 4*warp]);
                acc[0] += sv.x*snv; acc[1] += sv.y*snv;
                acc[2] += sv.z*snv; acc[3] += sv.w*snv;
            }
            #pragma unroll
            for (int k = 0; k < 4; k++) {
                int d = 4*warp + k;
                st[r_Tma + d*32 + lane] = 0.95f * st[r_Tma + d*32 + lane]
                                        + (0.05f / NMA) * acc[k];
            }
        }
        { float* t = M; M = Mn; Mn = t; }
        gbar(wg);
    }

    // ---- energy (final step only) ----
    {
        float a0[8], a1[8];
        #pragma unroll
        for (int k = 0; k < 8; k++) { a0[k] = sm[o_be1 + lane]; a1[k] = sm[o_be1 + lane + 32]; }
        #pragma unroll 2
        for (int d4 = 0; d4 < 8; d4++) {
            float u0 = sm[o_We1 + (4*d4+0)*64 + lane];
            float u1 = sm[o_We1 + (4*d4+1)*64 + lane];
            float u2 = sm[o_We1 + (4*d4+2)*64 + lane];
            float u3 = sm[o_We1 + (4*d4+3)*64 + lane];
            float x0 = sm[o_We1 + (4*d4+0)*64 + lane + 32];
            float x1 = sm[o_We1 + (4*d4+1)*64 + lane + 32];
            float x2 = sm[o_We1 + (4*d4+2)*64 + lane + 32];
            float x3 = sm[o_We1 + (4*d4+3)*64 + lane + 32];
            #pragma unroll
            for (int k = 0; k < 8; k++) {
                float4 s4 = ld4(&S[(warp + 8*k)*32 + 4*d4]);
                a0[k] += s4.x*u0 + s4.y*u1 + s4.z*u2 + s4.w*u3;
                a1[k] += s4.x*x0 + s4.y*x1 + s4.z*x2 + s4.w*x3;
            }
        }
        float part = 0.f;
        #pragma unroll
        for (int k = 0; k < 8; k++)
            part += tanhf(a0[k]) * sm[o_We2 + lane] + tanhf(a1[k]) * sm[o_We2 + lane + 32];
        part = warp_sum(part);
        if (lane == 0) misc[warp] = part;
        gbar(wg);
        if (tid_g == 0) {
            float tot = 0.f;
            #pragma unroll
            for (int w = 0; w < 8; w++) tot += misc[w];
            misc[16] = tot * (1.f / NMI) + be2v;
        }
        gbar(wg);
    }

    // ---- write outputs: micro | macro | tmi | tma | energy ----
    if (valid) {
        const long long off_macro = (long long)B * 2048;
        const long long off_tmi   = off_macro + (long long)B * 512;
        const long long off_tma   = off_tmi   + (long long)B * 1024;
        const long long off_en    = off_tma   + (long long)B * 1024;
        for (int i = tid_g; i < 2048; i += 256) out[(long long)b*2048 + i] = S[i];
        for (int i = tid_g; i < 512;  i += 256) out[off_macro + (long long)b*512 + i] = M[i];
        for (int i = tid_g; i < 1024; i += 256) {
            out[off_tmi + (long long)b*1024 + i] = st[r_Tmi + i];
            out[off_tma + (long long)b*1024 + i] = st[r_Tma + i];
        }
        if (tid_g == 0) out[off_en + b] = misc[16];
    }
}

extern "C" void kernel_launch(void* const* d_in, const int* in_sizes, int n_in,
                              void* d_out, int out_size)
{
    const int B = in_sizes[0] / (NMI * DD);
    cudaFuncSetAttribute(hm_kernel, cudaFuncAttributeMaxDynamicSharedMemorySize, SMEM_BYTES);
    hm_kernel<<<(B + 1) / 2, NT, SMEM_BYTES>>>(
        (const float*)d_in[0],  (const float*)d_in[1],  (const float*)d_in[2],
        (const float*)d_in[3],  (const float*)d_in[4],  (const float*)d_in[5],
        (const float*)d_in[6],  (const float*)d_in[7],  (const float*)d_in[8],
        (const float*)d_in[9],  (const float*)d_in[10], (const float*)d_in[11],
        (const float*)d_in[12], (const float*)d_in[13], (const float*)d_in[14],
        (const float*)d_in[15], (const float*)d_in[16], (const float*)d_in[17],
        (const float*)d_in[18], (const float*)d_in[19], (const float*)d_in[20],
        (const float*)d_in[21], (const float*)d_in[22], (const float*)d_in[23],
        (const int*)d_in[24],
        (float*)d_out, B);
}

// round 3
// speedup vs baseline: 1.7843x; 1.1407x over previous
#include <cuda_runtime.h>

#define NT 768
#define NG 3
#define NMI 64
#define NMA 16
#define DD 32

// ---- weight region (float offsets, shared by all groups) ----
#define o_WtdT  0
#define o_WqT   1024
#define o_WkT   2048
#define o_WvT   3072
#define o_WoT   4096
#define o_Wsmi  5120
#define o_Wami  6144
#define o_Wsma  7168
#define o_Wama  8192
#define o_Ami   9216
#define o_Ama   13312
#define o_btd   13568
#define o_lng   13600
#define o_lnb   13632
#define o_bo    13664
#define o_bmi   13696
#define o_bma   13728
#define o_bqkv  13760
#define W_FLOATS 13856

// ---- per-group state region (relative float offsets) ----
// sc aliases r_Sb (the dead half of the S double buffer during C-phase).
// Energy weights (We1/be1/We2) alias vp/qp after the step loop.
#define r_Sa    0
#define r_Sb    2048
#define r_Tmi   4096
#define r_Ma    5120
#define r_Mb    5632
#define r_Tma   6144
#define r_agg   7168
#define r_qp    9216
#define r_kpT   9728
#define r_vp    11808
#define r_misc  13856
#define ST_FLOATS 13920

#define SMEM_FLOATS (W_FLOATS + NG*ST_FLOATS)
#define SMEM_BYTES  (SMEM_FLOATS * 4)

__device__ __forceinline__ float warp_sum(float v) {
    #pragma unroll
    for (int o = 16; o; o >>= 1) v += __shfl_xor_sync(0xFFFFFFFFu, v, o);
    return v;
}
__device__ __forceinline__ float warp_max(float v) {
    #pragma unroll
    for (int o = 16; o; o >>= 1) v = fmaxf(v, __shfl_xor_sync(0xFFFFFFFFu, v, o));
    return v;
}
__device__ __forceinline__ void gbar(int wg) {
    asm volatile("bar.sync %0, 256;" :: "r"(wg + 1) : "memory");
}
__device__ __forceinline__ float4 ld4(const float* p) {
    return *reinterpret_cast<const float4*>(p);
}

__global__ __launch_bounds__(NT)
void hm_kernel(
    const float* __restrict__ g_micro, const float* __restrict__ g_macro,
    const float* __restrict__ g_tmi,   const float* __restrict__ g_tma,
    const float* __restrict__ W_td,    const float* __restrict__ b_td,
    const float* __restrict__ ln_g,    const float* __restrict__ ln_b,
    const float* __restrict__ Wqkv,    const float* __restrict__ bqkv,
    const float* __restrict__ Wo,      const float* __restrict__ bo,
    const float* __restrict__ A_mi,    const float* __restrict__ Ws_mi,
    const float* __restrict__ Wa_mi,   const float* __restrict__ b_mi,
    const float* __restrict__ A_ma,    const float* __restrict__ Ws_ma,
    const float* __restrict__ Wa_ma,   const float* __restrict__ b_ma,
    const float* __restrict__ We1,     const float* __restrict__ be1,
    const float* __restrict__ We2,     const float* __restrict__ be2,
    const int*   __restrict__ steps_p,
    float* __restrict__ out, int B)
{
    extern __shared__ float sm[];
    const int tid   = threadIdx.x;
    const int lane  = tid & 31;
    const int wg    = tid >> 8;           // batch group 0..2
    const int tid_g = tid & 255;
    const int warp  = tid_g >> 5;         // 0..7 within group

    int b = blockIdx.x * NG + wg;
    const bool valid = (b < B);
    if (!valid) b = B - 1;                // duplicate work, skip writes

    // ---- stage weights (all 768 threads) ----
    for (int i = tid; i < 1024; i += NT) {
        int d = i >> 5, e = i & 31;
        sm[o_WtdT + d*32 + e] = W_td[e*32 + d];
        sm[o_WqT  + d*32 + e] = Wqkv[e*32 + d];
        sm[o_WkT  + d*32 + e] = Wqkv[(32 + e)*32 + d];
        sm[o_WvT  + d*32 + e] = Wqkv[(64 + e)*32 + d];
        sm[o_WoT  + d*32 + e] = Wo[e*32 + d];
        sm[o_Wsmi + i] = Ws_mi[i];
        sm[o_Wami + i] = Wa_mi[i];
        sm[o_Wsma + i] = Ws_ma[i];
        sm[o_Wama + i] = Wa_ma[i];
    }
    for (int i = tid; i < 4096; i += NT) sm[o_Ami + i] = A_mi[i];
    for (int i = tid; i < 256;  i += NT) sm[o_Ama + i] = A_ma[i];
    if (tid < 32) {
        sm[o_btd + tid] = b_td[tid];  sm[o_lng + tid] = ln_g[tid];
        sm[o_lnb + tid] = ln_b[tid];  sm[o_bo  + tid] = bo[tid];
        sm[o_bmi + tid] = b_mi[tid];  sm[o_bma + tid] = b_ma[tid];
    }
    if (tid >= 32 && tid < 128) sm[o_bqkv + tid - 32] = bqkv[tid - 32];

    // ---- stage per-group state ----
    float* st = sm + W_FLOATS + wg * ST_FLOATS;
    for (int i = tid_g; i < 2048; i += 256) st[r_Sa + i] = g_micro[(long long)b*2048 + i];
    for (int i = tid_g; i < 1024; i += 256) {
        st[r_Tmi + i] = g_tmi[(long long)b*1024 + i];
        st[r_Tma + i] = g_tma[(long long)b*1024 + i];
    }
    for (int i = tid_g; i < 512; i += 256) st[r_Ma + i] = g_macro[(long long)b*512 + i];

    const int steps = *steps_p;
    const float be2v = *be2;
    float* S  = st + r_Sa;  float* Sn = st + r_Sb;
    float* M  = st + r_Ma;  float* Mn = st + r_Mb;
    float* agg = st + r_agg;
    float* qp  = st + r_qp;
    float* kpT = st + r_kpT;
    float* vp  = st + r_vp;
    float* misc = st + r_misc;
    __syncthreads();

    for (int it = 0; it < steps; ++it) {
        // ---- A: macro bias into micro ----
        if (tid_g < 32) {
            float s = 0.f;
            #pragma unroll
            for (int i = 0; i < NMA; i++) s += M[i*32 + tid_g];
            misc[tid_g] = s * (1.f / NMA);
        }
        gbar(wg);
        if (tid_g < 32) {
            float s = sm[o_btd + tid_g];
            #pragma unroll 8
            for (int d = 0; d < 32; d++) s += misc[d] * sm[o_WtdT + d*32 + tid_g];
            misc[32 + tid_g] = s;
        }
        gbar(wg);
        for (int i = tid_g; i < 2048; i += 256) S[i] += 0.1f * misc[32 + (i & 31)];
        gbar(wg);

        // ---- B1: agg = A_mi @ S ----
        {
            float acc[8];
            #pragma unroll
            for (int k = 0; k < 8; k++) acc[k] = 0.f;
            #pragma unroll 4
            for (int n4 = 0; n4 < 16; n4++) {
                float s0 = S[(4*n4+0)*32 + lane];
                float s1 = S[(4*n4+1)*32 + lane];
                float s2 = S[(4*n4+2)*32 + lane];
                float s3 = S[(4*n4+3)*32 + lane];
                #pragma unroll
                for (int k = 0; k < 8; k++) {
                    float4 a = ld4(&sm[o_Ami + (warp + 8*k)*64 + 4*n4]);
                    acc[k] += a.x*s0 + a.y*s1 + a.z*s2 + a.w*s3;
                }
            }
            #pragma unroll
            for (int k = 0; k < 8; k++) agg[(warp + 8*k)*32 + lane] = acc[k];
        }
        gbar(wg);

        // ---- B2+B3: update = tanh(agg@Wa + S@(Ws+Tmi) + b); Sn = l2norm(S + 0.1u) ----
        {
            float acc[8];
            #pragma unroll
            for (int k = 0; k < 8; k++) acc[k] = sm[o_bmi + lane];
            #pragma unroll 2
            for (int d4 = 0; d4 < 8; d4++) {
                float wa0 = sm[o_Wami + (4*d4+0)*32 + lane];
                float wa1 = sm[o_Wami + (4*d4+1)*32 + lane];
                float wa2 = sm[o_Wami + (4*d4+2)*32 + lane];
                float wa3 = sm[o_Wami + (4*d4+3)*32 + lane];
                float w0 = sm[o_Wsmi + (4*d4+0)*32 + lane] + st[r_Tmi + (4*d4+0)*32 + lane];
                float w1 = sm[o_Wsmi + (4*d4+1)*32 + lane] + st[r_Tmi + (4*d4+1)*32 + lane];
                float w2 = sm[o_Wsmi + (4*d4+2)*32 + lane] + st[r_Tmi + (4*d4+2)*32 + lane];
                float w3 = sm[o_Wsmi + (4*d4+3)*32 + lane] + st[r_Tmi + (4*d4+3)*32 + lane];
                #pragma unroll
                for (int k = 0; k < 8; k++) {
                    int n = warp + 8*k;
                    float4 ag = ld4(&agg[n*32 + 4*d4]);
                    float4 s4 = ld4(&S[n*32 + 4*d4]);
                    acc[k] += ag.x*wa0 + ag.y*wa1 + ag.z*wa2 + ag.w*wa3
                            + s4.x*w0  + s4.y*w1  + s4.z*w2  + s4.w*w3;
                }
            }
            #pragma unroll
            for (int k = 0; k < 8; k++) {
                int n = warp + 8*k;
                float v = S[n*32 + lane] + 0.1f * tanhf(acc[k]);
                float ss = warp_sum(v * v);
                Sn[n*32 + lane] = v * (1.f / (sqrtf(ss) + 1e-6f));
            }
        }
        gbar(wg);

        // ---- B4: micro trace (cols d = 4*warp + k, contiguous float4 bcast) ----
        {
            float acc[4] = {0.f, 0.f, 0.f, 0.f};
            #pragma unroll 8
            for (int n = 0; n < NMI; n++) {
                float snv = Sn[n*32 + lane];
                float4 sv = ld4(&S[n*32 + 4*warp]);
                acc[0] += sv.x*snv; acc[1] += sv.y*snv;
                acc[2] += sv.z*snv; acc[3] += sv.w*snv;
            }
            #pragma unroll
            for (int k = 0; k < 4; k++) {
                int d = 4*warp + k;
                st[r_Tmi + d*32 + lane] = 0.95f * st[r_Tmi + d*32 + lane]
                                        + (0.05f / NMI) * acc[k];
            }
        }
        { float* t = S; S = Sn; Sn = t; }
        float* sc = Sn;                     // dead S buffer hosts softmax probs
        gbar(wg);

        // ---- C1: qp = M @ Wq.T + bq ----
        {
            float a0 = sm[o_bqkv + lane], a1 = a0;
            #pragma unroll
            for (int d4 = 0; d4 < 8; d4++) {
                float q0 = sm[o_WqT + (4*d4+0)*32 + lane];
                float q1 = sm[o_WqT + (4*d4+1)*32 + lane];
                float q2 = sm[o_WqT + (4*d4+2)*32 + lane];
                float q3 = sm[o_WqT + (4*d4+3)*32 + lane];
                float4 m0 = ld4(&M[warp*32 + 4*d4]);
                float4 m1 = ld4(&M[(warp+8)*32 + 4*d4]);
                a0 += m0.x*q0 + m0.y*q1 + m0.z*q2 + m0.w*q3;
                a1 += m1.x*q0 + m1.y*q1 + m1.z*q2 + m1.w*q3;
            }
            qp[warp*32 + lane] = a0;
            qp[(warp+8)*32 + lane] = a1;
        }
        // ---- C2: kp (transposed, padded) + vp from new micro S ----
        {
            float ak[8], av[8];
            #pragma unroll
            for (int k = 0; k < 8; k++) { ak[k] = sm[o_bqkv + 32 + lane]; av[k] = sm[o_bqkv + 64 + lane]; }
            #pragma unroll 2
            for (int d4 = 0; d4 < 8; d4++) {
                float k0 = sm[o_WkT + (4*d4+0)*32 + lane];
                float k1 = sm[o_WkT + (4*d4+1)*32 + lane];
                float k2 = sm[o_WkT + (4*d4+2)*32 + lane];
                float k3 = sm[o_WkT + (4*d4+3)*32 + lane];
                float v0 = sm[o_WvT + (4*d4+0)*32 + lane];
                float v1 = sm[o_WvT + (4*d4+1)*32 + lane];
                float v2 = sm[o_WvT + (4*d4+2)*32 + lane];
                float v3 = sm[o_WvT + (4*d4+3)*32 + lane];
                #pragma unroll
                for (int k = 0; k < 8; k++) {
                    float4 s4 = ld4(&S[(warp + 8*k)*32 + 4*d4]);
                    ak[k] += s4.x*k0 + s4.y*k1 + s4.z*k2 + s4.w*k3;
                    av[k] += s4.x*v0 + s4.y*v1 + s4.z*v2 + s4.w*v3;
                }
            }
            #pragma unroll
            for (int k = 0; k < 8; k++) {
                int row = warp + 8*k;
                kpT[lane*65 + row] = ak[k];
                vp[row*32 + lane]  = av[k];
            }
        }
        gbar(wg);

        // ---- C3: scores + fused softmax ----
        {
            #pragma unroll
            for (int j = 0; j < 4; j++) {
                int r = warp + 8*j;          // 0..31
                int h = r >> 4, i = r & 15;
                float a0 = 0.f, a1 = 0.f;
                #pragma unroll
                for (int c = 0; c < 4; c++) {
                    float4 q4 = ld4(&qp[i*32 + h*16 + 4*c]);
                    int e = h*16 + 4*c;
                    a0 += q4.x * kpT[(e+0)*65 + lane] + q4.y * kpT[(e+1)*65 + lane]
                        + q4.z * kpT[(e+2)*65 + lane] + q4.w * kpT[(e+3)*65 + lane];
                    a1 += q4.x * kpT[(e+0)*65 + lane + 32] + q4.y * kpT[(e+1)*65 + lane + 32]
                        + q4.z * kpT[(e+2)*65 + lane + 32] + q4.w * kpT[(e+3)*65 + lane + 32];
                }
                a0 *= 0.25f; a1 *= 0.25f;
                float mx = warp_max(fmaxf(a0, a1));
                float e0 = __expf(a0 - mx), e1 = __expf(a1 - mx);
                float s = warp_sum(e0 + e1);
                float inv = 1.f / s;
                sc[r*64 + lane]      = e0 * inv;
                sc[r*64 + lane + 32] = e1 * inv;
            }
        }
        gbar(wg);

        // ---- C4a: att = attn @ v ----
        {
            int h = lane >> 4;
            float a0 = 0.f, a1 = 0.f;
            #pragma unroll 4
            for (int k4 = 0; k4 < 16; k4++) {
                float4 p0 = ld4(&sc[(h*16 + warp)*64 + 4*k4]);
                float4 p1 = ld4(&sc[(h*16 + warp + 8)*64 + 4*k4]);
                float v0 = vp[(4*k4+0)*32 + lane];
                float v1 = vp[(4*k4+1)*32 + lane];
                float v2 = vp[(4*k4+2)*32 + lane];
                float v3 = vp[(4*k4+3)*32 + lane];
                a0 += p0.x*v0 + p0.y*v1 + p0.z*v2 + p0.w*v3;
                a1 += p1.x*v0 + p1.y*v1 + p1.z*v2 + p1.w*v3;
            }
            agg[warp*32 + lane] = a0;
            agg[(warp+8)*32 + lane] = a1;
        }
        gbar(wg);

        // ---- C4b: out proj + residual + layernorm -> Mn ----
        {
            #pragma unroll
            for (int k = 0; k < 2; k++) {
                int i = warp + 8*k;
                float acc = sm[o_bo + lane];
                #pragma unroll
                for (int d4 = 0; d4 < 8; d4++) {
                    float o0 = sm[o_WoT + (4*d4+0)*32 + lane];
                    float o1 = sm[o_WoT + (4*d4+1)*32 + lane];
                    float o2 = sm[o_WoT + (4*d4+2)*32 + lane];
                    float o3 = sm[o_WoT + (4*d4+3)*32 + lane];
                    float4 g4 = ld4(&agg[i*32 + 4*d4]);
                    acc += g4.x*o0 + g4.y*o1 + g4.z*o2 + g4.w*o3;
                }
                float x = M[i*32 + lane] + acc;
                float mu = warp_sum(x) * (1.f / 32.f);
                float c = x - mu;
                float var = warp_sum(c * c) * (1.f / 32.f);
                Mn[i*32 + lane] = c * rsqrtf(var + 1e-5f) * sm[o_lng + lane] + sm[o_lnb + lane];
            }
        }
        gbar(wg);
        { float* t = M; M = Mn; Mn = t; }

        // ---- D1: macro agg = A_ma @ M ----
        {
            float a0 = 0.f, a1 = 0.f;
            #pragma unroll
            for (int n4 = 0; n4 < 4; n4++) {
                float s0 = M[(4*n4+0)*32 + lane];
                float s1 = M[(4*n4+1)*32 + lane];
                float s2 = M[(4*n4+2)*32 + lane];
                float s3 = M[(4*n4+3)*32 + lane];
                float4 aa = ld4(&sm[o_Ama + warp*16 + 4*n4]);
                float4 ab = ld4(&sm[o_Ama + (warp+8)*16 + 4*n4]);
                a0 += aa.x*s0 + aa.y*s1 + aa.z*s2 + aa.w*s3;
                a1 += ab.x*s0 + ab.y*s1 + ab.z*s2 + ab.w*s3;
            }
            agg[warp*32 + lane] = a0;
            agg[(warp+8)*32 + lane] = a1;
        }
        gbar(wg);

        // ---- D2: macro update + l2norm -> Mn ----
        {
            float acc0 = sm[o_bma + lane], acc1 = acc0;
            #pragma unroll 2
            for (int d4 = 0; d4 < 8; d4++) {
                float wa0 = sm[o_Wama + (4*d4+0)*32 + lane];
                float wa1 = sm[o_Wama + (4*d4+1)*32 + lane];
                float wa2 = sm[o_Wama + (4*d4+2)*32 + lane];
                float wa3 = sm[o_Wama + (4*d4+3)*32 + lane];
                float w0 = sm[o_Wsma + (4*d4+0)*32 + lane] + st[r_Tma + (4*d4+0)*32 + lane];
                float w1 = sm[o_Wsma + (4*d4+1)*32 + lane] + st[r_Tma + (4*d4+1)*32 + lane];
                float w2 = sm[o_Wsma + (4*d4+2)*32 + lane] + st[r_Tma + (4*d4+2)*32 + lane];
                float w3 = sm[o_Wsma + (4*d4+3)*32 + lane] + st[r_Tma + (4*d4+3)*32 + lane];
                float4 g0 = ld4(&agg[warp*32 + 4*d4]);
                float4 m0 = ld4(&M[warp*32 + 4*d4]);
                float4 g1 = ld4(&agg[(warp+8)*32 + 4*d4]);
                float4 m1 = ld4(&M[(warp+8)*32 + 4*d4]);
                acc0 += g0.x*wa0 + g0.y*wa1 + g0.z*wa2 + g0.w*wa3
                      + m0.x*w0  + m0.y*w1  + m0.z*w2  + m0.w*w3;
                acc1 += g1.x*wa0 + g1.y*wa1 + g1.z*wa2 + g1.w*wa3
                      + m1.x*w0  + m1.y*w1  + m1.z*w2  + m1.w*w3;
            }
            {
                float v = M[warp*32 + lane] + 0.1f * tanhf(acc0);
                float ss = warp_sum(v * v);
                Mn[warp*32 + lane] = v * (1.f / (sqrtf(ss) + 1e-6f));
            }
            {
                float v = M[(warp+8)*32 + lane] + 0.1f * tanhf(acc1);
                float ss = warp_sum(v * v);
                Mn[(warp+8)*32 + lane] = v * (1.f / (sqrtf(ss) + 1e-6f));
            }
        }
        gbar(wg);

        // ---- D4: macro trace (cols d = 4*warp + k) ----
        {
            float acc[4] = {0.f, 0.f, 0.f, 0.f};
            #pragma unroll
            for (int n = 0; n < NMA; n++) {
                float snv = Mn[n*32 + lane];
                float4 sv = ld4(&M[n*32 + 4*warp]);
                acc[0] += sv.x*snv; acc[1] += sv.y*snv;
                acc[2] += sv.z*snv; acc[3] += sv.w*snv;
            }
            #pragma unroll
            for (int k = 0; k < 4; k++) {
                int d = 4*warp + k;
                st[r_Tma + d*32 + lane] = 0.95f * st[r_Tma + d*32 + lane]
                                        + (0.05f / NMA) * acc[k];
            }
        }
        { float* t = M; M = Mn; Mn = t; }
        gbar(wg);
    }

    // ---- energy (final step only): load We1/be1/We2 into dead vp/qp scratch ----
    {
        for (int i = tid_g; i < 2048; i += 256) vp[i] = We1[i];
        if (tid_g < 64) { qp[tid_g] = be1[tid_g]; qp[64 + tid_g] = We2[tid_g]; }
        gbar(wg);

        float a0[8], a1[8];
        #pragma unroll
        for (int k = 0; k < 8; k++) { a0[k] = qp[lane]; a1[k] = qp[lane + 32]; }
        #pragma unroll 2
        for (int d4 = 0; d4 < 8; d4++) {
            float u0 = vp[(4*d4+0)*64 + lane];
            float u1 = vp[(4*d4+1)*64 + lane];
            float u2 = vp[(4*d4+2)*64 + lane];
            float u3 = vp[(4*d4+3)*64 + lane];
            float x0 = vp[(4*d4+0)*64 + lane + 32];
            float x1 = vp[(4*d4+1)*64 + lane + 32];
            float x2 = vp[(4*d4+2)*64 + lane + 32];
            float x3 = vp[(4*d4+3)*64 + lane + 32];
            #pragma unroll
            for (int k = 0; k < 8; k++) {
                float4 s4 = ld4(&S[(warp + 8*k)*32 + 4*d4]);
                a0[k] += s4.x*u0 + s4.y*u1 + s4.z*u2 + s4.w*u3;
                a1[k] += s4.x*x0 + s4.y*x1 + s4.z*x2 + s4.w*x3;
            }
        }
        float part = 0.f;
        #pragma unroll
        for (int k = 0; k < 8; k++)
            part += tanhf(a0[k]) * qp[64 + lane] + tanhf(a1[k]) * qp[96 + lane];
        part = warp_sum(part);
        if (lane == 0) misc[warp] = part;
        gbar(wg);
        if (tid_g == 0) {
            float tot = 0.f;
            #pragma unroll
            for (int w = 0; w < 8; w++) tot += misc[w];
            misc[16] = tot * (1.f / NMI) + be2v;
        }
        gbar(wg);
    }

    // ---- write outputs: micro | macro | tmi | tma | energy ----
    if (valid) {
        const long long off_macro = (long long)B * 2048;
        const long long off_tmi   = off_macro + (long long)B * 512;
        const long long off_tma   = off_tmi   + (long long)B * 1024;
        const long long off_en    = off_tma   + (long long)B * 1024;
        for (int i = tid_g; i < 2048; i += 256) out[(long long)b*2048 + i] = S[i];
        for (int i = tid_g; i < 512;  i += 256) out[off_macro + (long long)b*512 + i] = M[i];
        for (int i = tid_g; i < 1024; i += 256) {
            out[off_tmi + (long long)b*1024 + i] = st[r_Tmi + i];
            out[off_tma + (long long)b*1024 + i] = st[r_Tma + i];
        }
        if (tid_g == 0) out[off_en + b] = misc[16];
    }
}

extern "C" void kernel_launch(void* const* d_in, const int* in_sizes, int n_in,
                              void* d_out, int out_size)
{
    const int B = in_sizes[0] / (NMI * DD);
    cudaFuncSetAttribute(hm_kernel, cudaFuncAttributeMaxDynamicSharedMemorySize, SMEM_BYTES);
    hm_kernel<<<(B + NG - 1) / NG, NT, SMEM_BYTES>>>(
        (const float*)d_in[0],  (const float*)d_in[1],  (const float*)d_in[2],
        (const float*)d_in[3],  (const float*)d_in[4],  (const float*)d_in[5],
        (const float*)d_in[6],  (const float*)d_in[7],  (const float*)d_in[8],
        (const float*)d_in[9],  (const float*)d_in[10], (const float*)d_in[11],
        (const float*)d_in[12], (const float*)d_in[13], (const float*)d_in[14],
        (const float*)d_in[15], (const float*)d_in[16], (const float*)d_in[17],
        (const float*)d_in[18], (const float*)d_in[19], (const float*)d_in[20],
        (const float*)d_in[21], (const float*)d_in[22], (const float*)d_in[23],
        (const int*)d_in[24],
        (float*)d_out, B);
}